// round 10
// baseline (speedup 1.0000x reference)
#include <cuda_runtime.h>
#include <cstdint>

// Problem constants
static constexpr int B_   = 4;
static constexpr int W_   = 12;
static constexpr int N_   = 1024;
static constexpr int FIN_ = 32;
static constexpr int FOUT_= 32;
static constexpr int H_   = 256;
static constexpr int BW_  = B_ * W_;        // 48
static constexpr int D_   = N_ * FOUT_;     // 32768
static constexpr int KC_  = 64;             // split-K chunks for gates GEMM (k=512 each)
static constexpr int KQ_  = 8;              // split-K for gcn GEMM (k=128 each)

// ---------------- packed f32x2 helpers ----------------
#define FMA2(acc, a, b) asm("fma.rn.f32x2 %0, %1, %2, %0;" : "+l"(acc) : "l"(a), "l"(b))
#define PACK2(d, f)     asm("mov.b64 %0, {%1, %1};" : "=l"(d) : "f"(f))
#define UNPACK2(lo, hi, d) asm("mov.b64 {%0, %1}, %2;" : "=f"(lo), "=f"(hi) : "l"(d))

// ---------------- cp.async helpers ----------------
__device__ __forceinline__ void cp16(uint32_t dst, const void* src) {
    asm volatile("cp.async.cg.shared.global [%0], [%1], 16;" :: "r"(dst), "l"(src));
}
#define CP_COMMIT() asm volatile("cp.async.commit_group;")
#define CP_WAIT1()  asm volatile("cp.async.wait_group 1;")
#define CP_WAIT0()  asm volatile("cp.async.wait_group 0;")

// ---------------- scratch (static device globals; no allocation) ----------------
__device__ float g_deg[BW_ * N_];
__device__ float g_P[(size_t)BW_ * N_ * FOUT_];
__device__ float g_xpart[(size_t)KQ_ * BW_ * N_ * FOUT_];   // gcn split-K partials
__device__ float g_XT[(size_t)D_ * BW_];                    // X transposed: [k][wb]
__device__ float g_part[(size_t)KC_ * BW_ * 4 * H_];        // gates split-K partials
__device__ float g_gates[BW_ * 4 * H_];
__device__ float g_hn[B_ * H_];
__device__ float g_out[B_ * D_];
__device__ float g_s1[B_ * N_];
__device__ float g_s2[B_ * N_];

// ---------------- K1: fused degree + P -------------------------------------------
__global__ void k_degP(const float* __restrict__ shots, const float* __restrict__ node,
                       const float* __restrict__ gcn_w) {
    __shared__ float gw[FIN_ * FOUT_];
    int r0 = blockIdx.x * 8;
    int w  = (r0 / N_) % W_;            // rows bw-major: bw = b*W + w
    for (int i = threadIdx.x; i < FIN_ * FOUT_; i += 256)
        gw[i] = gcn_w[(size_t)w * FIN_ * FOUT_ + i];
    __syncthreads();
    int warp = threadIdx.x >> 5, lane = threadIdx.x & 31;
    int r = r0 + warp;
    const float4* p = (const float4*)(shots + (size_t)r * N_);
    float s = 0.f;
#pragma unroll
    for (int i = 0; i < 8; i++) {
        float4 v = p[lane + 32 * i];
        s += v.x + v.y + v.z + v.w;
    }
#pragma unroll
    for (int o = 16; o; o >>= 1) s += __shfl_xor_sync(0xffffffffu, s, o);
    float d = 1.0f / sqrtf(1.0f + s);
    if (lane == 0) g_deg[r] = d;

    float nv = node[(size_t)r * FIN_ + lane];
    float acc = 0.f;
#pragma unroll
    for (int f = 0; f < FIN_; f++) {
        float x = __shfl_sync(0xffffffffu, nv, f);
        acc += x * gw[f * FOUT_ + lane];
    }
    g_P[(size_t)r * FOUT_ + lane] = d * acc;
}

// ---------------- K3: xpart[kq] = shots[n, kq-chunk] @ P[kq-chunk, :] ----------
static constexpr int AS_ = 292;   // A_shT row stride (floats)
__global__ __launch_bounds__(64) void k_gcn(const float* __restrict__ shots) {
    __shared__ __align__(16) float AT[16 * AS_];   // [kk][f(row)]
    __shared__ __align__(16) float PS[16 * 32];    // [kk][col]
    int bw = blockIdx.x >> 3;
    int n0 = (blockIdx.x & 7) << 7;      // * 128
    int kq = blockIdx.y;
    int t = threadIdx.x;
    int tx = t & 3;
    int ty = t >> 2;
    const float* Abase = shots + (size_t)bw * N_ * N_;
    const float* Pbase = g_P + (size_t)bw * N_ * FOUT_;

    unsigned long long acc[4][8];
#pragma unroll
    for (int i = 0; i < 4; i++)
#pragma unroll
        for (int j = 0; j < 8; j++) acc[i][j] = 0ull;

    const int r8 = ty * 8;
    const int fr = r8 + ((r8 >> 5) << 2);

    for (int k0 = kq * 128; k0 < kq * 128 + 128; k0 += 16) {
#pragma unroll
        for (int i = 0; i < 8; i++) {
            int idx = t + 64 * i;
            int rr = idx >> 2, q = idx & 3;
            float4 v = *(const float4*)(Abase + (size_t)(n0 + rr) * N_ + k0 + 4 * q);
            int f = rr + ((rr >> 5) << 2);
            AT[(4 * q + 0) * AS_ + f] = v.x;
            AT[(4 * q + 1) * AS_ + f] = v.y;
            AT[(4 * q + 2) * AS_ + f] = v.z;
            AT[(4 * q + 3) * AS_ + f] = v.w;
        }
#pragma unroll
        for (int i = 0; i < 2; i++) {
            int idx = t + 64 * i;
            int kk = idx >> 3, c = idx & 7;
            *(float4*)&PS[kk * 32 + 4 * c] =
                *(const float4*)(Pbase + (size_t)(k0 + kk) * 32 + 4 * c);
        }
        __syncthreads();
#pragma unroll 4
        for (int kk = 0; kk < 16; kk++) {
            ulonglong2 aA = *(const ulonglong2*)&AT[kk * AS_ + fr];
            ulonglong2 aB = *(const ulonglong2*)&AT[kk * AS_ + fr + 4];
            float4 p0 = *(const float4*)&PS[kk * 32 + tx * 8];
            float4 p1 = *(const float4*)&PS[kk * 32 + tx * 8 + 4];
            unsigned long long ap[4];
            ap[0] = aA.x; ap[1] = aA.y; ap[2] = aB.x; ap[3] = aB.y;
            unsigned long long bb[8];
            PACK2(bb[0], p0.x); PACK2(bb[1], p0.y); PACK2(bb[2], p0.z); PACK2(bb[3], p0.w);
            PACK2(bb[4], p1.x); PACK2(bb[5], p1.y); PACK2(bb[6], p1.z); PACK2(bb[7], p1.w);
#pragma unroll
            for (int i = 0; i < 4; i++)
#pragma unroll
                for (int j = 0; j < 8; j++) FMA2(acc[i][j], ap[i], bb[j]);
        }
        __syncthreads();
    }

    float* Xp = g_xpart + (size_t)kq * BW_ * N_ * FOUT_ + (size_t)bw * N_ * FOUT_;
#pragma unroll
    for (int i = 0; i < 4; i++) {
        int ne = n0 + r8 + 2 * i;
        float lo[8], hi[8];
#pragma unroll
        for (int j = 0; j < 8; j++) UNPACK2(lo[j], hi[j], acc[i][j]);
        float4 o0 = {lo[0], lo[1], lo[2], lo[3]};
        float4 o1 = {lo[4], lo[5], lo[6], lo[7]};
        float4 o2 = {hi[0], hi[1], hi[2], hi[3]};
        float4 o3 = {hi[4], hi[5], hi[6], hi[7]};
        *(float4*)(Xp + (size_t)ne * 32 + tx * 8) = o0;
        *(float4*)(Xp + (size_t)ne * 32 + tx * 8 + 4) = o1;
        *(float4*)(Xp + (size_t)(ne + 1) * 32 + tx * 8) = o2;
        *(float4*)(Xp + (size_t)(ne + 1) * 32 + tx * 8 + 4) = o3;
    }
}

// ---------------- K3f: XT[k][wb] = d[n]*(sum_kq xpart + P), smem-tiled transpose -
// grid 256 blocks x 256 thr; block handles 128 consecutive k (= n*32+o) rows.
__global__ void k_xfin(void) {
    __shared__ float tile[128 * 49];   // [rr][wb'] (stride 49: conflict-free)
    int rt = blockIdx.x * 128;
    int t = threadIdx.x;
    // gather phase: 24 passes over (bw, rr)
#pragma unroll 4
    for (int pass = 0; pass < 24; pass++) {
        int p = pass * 256 + t;
        int bw = p >> 7, rr = p & 127;
        int r = rt + rr;
        float s = g_P[(size_t)bw * D_ + r];
#pragma unroll
        for (int kq = 0; kq < KQ_; kq++)
            s += g_xpart[(size_t)kq * BW_ * D_ + (size_t)bw * D_ + r];
        s *= g_deg[bw * N_ + (r >> 5)];
        int w = bw % W_, b = bw / W_;
        tile[rr * 49 + (w * B_ + b)] = s;
    }
    __syncthreads();
    // scatter phase: contiguous writes to g_XT
#pragma unroll 4
    for (int pass = 0; pass < 24; pass++) {
        int o = pass * 256 + t;
        int rr = o / 48, c = o % 48;
        g_XT[(size_t)(rt + rr) * BW_ + c] = tile[rr * 49 + c];
    }
}

// ---------------- K4: gates_x = X @ w_ih^T  (dual cp.async, 4 blocks/SM) --------
// Block = 48 wb x 128 g over K-chunk 512 (16 stages of 32 k). 192 threads.
// Thread tile: 8 wb (4 packed pairs) x 4 g (g = gl + 32j). Grid (8, 64).
static constexpr int WROW_ = 36;                  // W smem row stride (floats)
static constexpr int WBUF_ = 128 * WROW_;         // 4608 floats per buffer
static constexpr int XS_   = 52;                  // XT smem row stride
static constexpr int XBUF_ = 32 * XS_;            // 1664 floats per buffer
static constexpr int GATES_SMEM = (2 * WBUF_ + 2 * XBUF_) * 4;   // 50176 B

__global__ __launch_bounds__(192, 4) void k_gates(const float* __restrict__ w_ih) {
    extern __shared__ __align__(16) float sm[];
    float* WS = sm;                 // [2][128][36]
    float* XT = sm + 2 * WBUF_;     // [2][32][52]
    const int g0 = blockIdx.x * 128;
    const int kc = blockIdx.y;
    const int kbase = kc * 512;
    const int t = threadIdx.x;
    const int warp = t >> 5, gl = t & 31;
    const int wb0 = warp * 8;
    const uint32_t ws_smem = (uint32_t)__cvta_generic_to_shared(WS);
    const uint32_t xt_smem = (uint32_t)__cvta_generic_to_shared(XT);

    unsigned long long acc[4][4];
#pragma unroll
    for (int i = 0; i < 4; i++)
#pragma unroll
        for (int j = 0; j < 4; j++) acc[i][j] = 0ull;

    // W: 128 rows x 32 k = 1024 x 16B cp.async; X: 32 rows x 48 wb = 384 x 16B
#define STAGE(bufi, k0)                                                            \
    do {                                                                           \
        for (int idx = t; idx < 1024; idx += 192) {                                \
            int g = idx >> 3, q = idx & 7;                                         \
            cp16(ws_smem + ((bufi) * WBUF_ + g * WROW_ + 4 * q) * 4,               \
                 w_ih + (size_t)(g0 + g) * D_ + (k0) + 4 * q);                     \
        }                                                                          \
        for (int idx = t; idx < 384; idx += 192) {                                 \
            int kk = idx / 12, q = idx % 12;                                       \
            cp16(xt_smem + ((bufi) * XBUF_ + kk * XS_ + 4 * q) * 4,                \
                 g_XT + (size_t)((k0) + kk) * BW_ + 4 * q);                        \
        }                                                                          \
        CP_COMMIT();                                                               \
    } while (0)

    STAGE(0, kbase);

    for (int s = 0; s < 16; s++) {
        int buf = s & 1;
        __syncthreads();   // previous compute done -> other buffer free
        if (s < 15) {
            STAGE(buf ^ 1, kbase + 32 * (s + 1));
            CP_WAIT1();
        } else {
            CP_WAIT0();
        }
        __syncthreads();
        const float* WB = WS + buf * WBUF_;
        const float* XB = XT + buf * XBUF_;
#pragma unroll
        for (int kkc = 0; kkc < 8; kkc++) {
            unsigned long long ap[4][4];
#pragma unroll
            for (int kk = 0; kk < 4; kk++) {
                int krow = kkc * 4 + kk;
                ulonglong2 xA = *(const ulonglong2*)&XB[krow * XS_ + wb0];
                ulonglong2 xB2 = *(const ulonglong2*)&XB[krow * XS_ + wb0 + 4];
                ap[kk][0] = xA.x; ap[kk][1] = xA.y; ap[kk][2] = xB2.x; ap[kk][3] = xB2.y;
            }
#pragma unroll
            for (int j = 0; j < 4; j++) {
                float4 v = *(const float4*)&WB[(gl + 32 * j) * WROW_ + kkc * 4];
                float wf[4] = {v.x, v.y, v.z, v.w};
#pragma unroll
                for (int kk = 0; kk < 4; kk++) {
                    unsigned long long b2;
                    PACK2(b2, wf[kk]);
#pragma unroll
                    for (int i = 0; i < 4; i++) FMA2(acc[i][j], ap[kk][i], b2);
                }
            }
        }
    }
#undef STAGE

    // epilogue -> split-K partials
#pragma unroll
    for (int i = 0; i < 4; i++) {
#pragma unroll
        for (int j = 0; j < 4; j++) {
            float lo, hi;
            UNPACK2(lo, hi, acc[i][j]);
            int gcol = g0 + gl + 32 * j;
            g_part[((size_t)kc * BW_ + wb0 + 2 * i) * 1024 + gcol] = lo;
            g_part[((size_t)kc * BW_ + wb0 + 2 * i + 1) * 1024 + gcol] = hi;
        }
    }
}

// ---------------- K4r: reduce split-K + biases ----------------------------------
__global__ void k_greduce(const float* __restrict__ b_ih, const float* __restrict__ b_hh) {
    int i = blockIdx.x * 256 + threadIdx.x;   // 0..49151
    int g = i & 1023;
    float s = b_ih[g] + b_hh[g];
#pragma unroll 8
    for (int kc = 0; kc < KC_; kc++) s += g_part[(size_t)kc * BW_ * 1024 + i];
    g_gates[i] = s;
}

// ---------------- K5: fused 12-step LSTM (one block per batch, smem h) ----------
// grid B_ x 256 threads; thread = hidden unit j; h double-buffered in smem.
__global__ __launch_bounds__(256) void k_lstm(const float* __restrict__ w_hh) {
    __shared__ __align__(16) float hsh[2][H_];
    int b = blockIdx.x;
    int j = threadIdx.x;
    const unsigned long long* wr[4];
#pragma unroll
    for (int r = 0; r < 4; r++)
        wr[r] = (const unsigned long long*)(w_hh + (size_t)(r * H_ + j) * H_);
    float cc = 0.f;
    hsh[0][j] = 0.f;
    __syncthreads();

    for (int w = 0; w < W_; w++) {
        int p = w & 1;
        const float* gx = g_gates + ((size_t)(w * B_ + b)) * 4 * H_;
        unsigned long long a2[4] = {0ull, 0ull, 0ull, 0ull};
        const unsigned long long* h2 = (const unsigned long long*)hsh[p];
#pragma unroll 16
        for (int k = 0; k < H_ / 2; k++) {
            unsigned long long hv = h2[k];
#pragma unroll
            for (int r = 0; r < 4; r++) FMA2(a2[r], wr[r][k], hv);
        }
        float acc[4];
#pragma unroll
        for (int r = 0; r < 4; r++) {
            float lo, hi;
            UNPACK2(lo, hi, a2[r]);
            acc[r] = gx[r * H_ + j] + lo + hi;
        }
        float ig = 1.0f / (1.0f + expf(-acc[0]));
        float fg = 1.0f / (1.0f + expf(-acc[1]));
        float gg = tanhf(acc[2]);
        float og = 1.0f / (1.0f + expf(-acc[3]));
        cc = fg * cc + ig * gg;
        hsh[p ^ 1][j] = og * tanhf(cc);
        __syncthreads();
    }
    g_hn[b * H_ + j] = hsh[0][j];   // w=11 writes buffer 0
}

// ---------------- K6: out[b, r] = hn[b,:]·f1_w[r,:] + f1_b[r] -------------------
__global__ void k_out(const float* __restrict__ f1_w, const float* __restrict__ f1_b) {
    __shared__ __align__(16) float hsh[B_ * H_];
    for (int i = threadIdx.x; i < B_ * H_; i += 256) hsh[i] = g_hn[i];
    __syncthreads();
    int warp = threadIdx.x >> 5, lane = threadIdx.x & 31;
    int r = blockIdx.x * 8 + warp;
    const float4* Wr = (const float4*)(f1_w + (size_t)r * H_);
    float a[B_] = {0.f, 0.f, 0.f, 0.f};
#pragma unroll
    for (int t = 0; t < 2; t++) {
        int idx = lane + 32 * t;
        float4 wv = Wr[idx];
#pragma unroll
        for (int b = 0; b < B_; b++) {
            float4 hv = *(const float4*)&hsh[b * H_ + idx * 4];
            a[b] += wv.x * hv.x + wv.y * hv.y + wv.z * hv.z + wv.w * hv.w;
        }
    }
#pragma unroll
    for (int b = 0; b < B_; b++) {
#pragma unroll
        for (int o = 16; o; o >>= 1) a[b] += __shfl_xor_sync(0xffffffffu, a[b], o);
    }
    if (lane == 0) {
        float bb = f1_b[r];
#pragma unroll
        for (int b = 0; b < B_; b++) g_out[(size_t)b * D_ + r] = a[b] + bb;
    }
}

// ---------------- K6c: s1[b,n], s2[b,n] -----------------------------------------
__global__ void k_s(const float* __restrict__ f2_w) {
    int idx = blockIdx.x * 256 + threadIdx.x;
    const float4* v4 = (const float4*)(g_out + (size_t)idx * FOUT_);
    const float4* w1 = (const float4*)(f2_w);
    const float4* w2 = (const float4*)(f2_w + FOUT_);
    float s1 = 0.f, s2 = 0.f;
#pragma unroll
    for (int t = 0; t < 8; t++) {
        float4 v = v4[t], a = w1[t], b = w2[t];
        s1 += v.x * a.x + v.y * a.y + v.z * a.z + v.w * a.w;
        s2 += v.x * b.x + v.y * b.y + v.z * b.z + v.w * b.w;
    }
    g_s1[idx] = s1;
    g_s2[idx] = s2;
}

// ---------------- K7: scores, keep mask, L1 row-normalize, write output ----------
__global__ void k_final(float* __restrict__ res, const float* __restrict__ f2_b) {
    __shared__ float s1s[N_], s2s[N_];
    __shared__ float wsum[8];
    __shared__ float total;
    int b = blockIdx.x >> 10;
    int i = blockIdx.x & 1023;
    for (int t = threadIdx.x; t < N_; t += 256) {
        s1s[t] = g_s1[b * N_ + t];
        s2s[t] = g_s2[b * N_ + t];
    }
    __syncthreads();
    float bias = f2_b[0];
    float s1i = s1s[i], s2i = s2s[i];
    float v[4];
    float asum = 0.f;
#pragma unroll
    for (int t = 0; t < 4; t++) {
        int j = threadIdx.x + t * 256;
        float sc = s1i + s2s[j] + bias;
        float st = s1s[j] + s2i + bias;
        float val;
        if (i == j) {
            val = sc;
        } else {
            bool keep = (i < j) ? (sc >= st && sc > 0.f) : (sc > st && sc >= 0.f);
            val = keep ? sc : 0.f;
        }
        v[t] = val;
        asum += fabsf(val);
    }
    int warp = threadIdx.x >> 5, lane = threadIdx.x & 31;
#pragma unroll
    for (int o = 16; o; o >>= 1) asum += __shfl_xor_sync(0xffffffffu, asum, o);
    if (lane == 0) wsum[warp] = asum;
    __syncthreads();
    if (threadIdx.x == 0) {
        float s = 0.f;
#pragma unroll
        for (int k = 0; k < 8; k++) s += wsum[k];
        total = s;
    }
    __syncthreads();
    float inv = 1.0f / fmaxf(total, 1e-12f);
    float* row = res + ((size_t)b * N_ + i) * N_;
#pragma unroll
    for (int t = 0; t < 4; t++) row[threadIdx.x + t * 256] = v[t] * inv;
}

// =================================================================================
extern "C" void kernel_launch(void* const* d_in, const int* in_sizes, int n_in,
                              void* d_out, int out_size) {
    const float* shots = (const float*)d_in[0];
    const float* node  = (const float*)d_in[1];
    // d_in[2] = 'a' (unused by reference)
    const float* gcn_w = (const float*)d_in[3];
    const float* w_ih  = (const float*)d_in[4];
    const float* w_hh  = (const float*)d_in[5];
    const float* b_ih  = (const float*)d_in[6];
    const float* b_hh  = (const float*)d_in[7];
    const float* f1_w  = (const float*)d_in[8];
    const float* f1_b  = (const float*)d_in[9];
    const float* f2_w  = (const float*)d_in[10];
    const float* f2_b  = (const float*)d_in[11];
    float* res = (float*)d_out;

    cudaFuncSetAttribute(k_gates, cudaFuncAttributeMaxDynamicSharedMemorySize, GATES_SMEM);

    k_degP<<<BW_ * N_ / 8, 256>>>(shots, node, gcn_w);   // #1
    k_gcn<<<dim3(BW_ * 8, KQ_), 64>>>(shots);            // #2
    k_xfin<<<D_ / 128, 256>>>();                         // #3
    k_gates<<<dim3(8, KC_), 192, GATES_SMEM>>>(w_ih);    // #4  <- ncu sample slot
    k_greduce<<<BW_ * 4 * H_ / 256, 256>>>(b_ih, b_hh);  // #5
    k_lstm<<<B_, H_>>>(w_hh);                            // #6
    k_out<<<D_ / 8, 256>>>(f1_w, f1_b);                  // #7
    k_s<<<B_ * N_ / 256, 256>>>(f2_w);                   // #8
    k_final<<<B_ * N_, 256>>>(res, f2_b);                // #9
}

// round 11
// speedup vs baseline: 2.0352x; 2.0352x over previous
#include <cuda_runtime.h>
#include <cstdint>

// Problem constants
static constexpr int B_   = 4;
static constexpr int W_   = 12;
static constexpr int N_   = 1024;
static constexpr int FIN_ = 32;
static constexpr int FOUT_= 32;
static constexpr int H_   = 256;
static constexpr int BW_  = B_ * W_;        // 48
static constexpr int D_   = N_ * FOUT_;     // 32768
static constexpr int KC_  = 64;             // split-K chunks for gates GEMM (k=512 each)
static constexpr int KQ_  = 8;              // split-K for gcn GEMM (k=128 each)

// ---------------- packed f32x2 helpers ----------------
#define FMA2(acc, a, b) asm("fma.rn.f32x2 %0, %1, %2, %0;" : "+l"(acc) : "l"(a), "l"(b))
#define PACK2(d, f)     asm("mov.b64 %0, {%1, %1};" : "=l"(d) : "f"(f))
#define UNPACK2(lo, hi, d) asm("mov.b64 {%0, %1}, %2;" : "=f"(lo), "=f"(hi) : "l"(d))

// ---------------- cp.async helpers ----------------
__device__ __forceinline__ void cp16(uint32_t dst, const void* src) {
    asm volatile("cp.async.cg.shared.global [%0], [%1], 16;" :: "r"(dst), "l"(src));
}
#define CP_COMMIT() asm volatile("cp.async.commit_group;")
#define CP_WAIT1()  asm volatile("cp.async.wait_group 1;")
#define CP_WAIT0()  asm volatile("cp.async.wait_group 0;")

// ---------------- scratch (static device globals; no allocation) ----------------
__device__ float g_deg[BW_ * N_];
__device__ float g_P[(size_t)BW_ * N_ * FOUT_];
__device__ float g_xpart[(size_t)KQ_ * BW_ * N_ * FOUT_];   // gcn split-K partials
__device__ float g_XT[(size_t)D_ * BW_];                    // X transposed: [k][wb]
__device__ float g_part[(size_t)KC_ * BW_ * 4 * H_];        // gates split-K partials
__device__ float g_gates[BW_ * 4 * H_];
__device__ float g_whhT[(size_t)H_ * 4 * H_];               // w_hh transposed: [k][g]
__device__ float g_hn[B_ * H_];
__device__ float g_out[B_ * D_];
__device__ float g_s1[B_ * N_];
__device__ float g_s2[B_ * N_];

// ---------------- K0: transpose w_hh [4H][H] -> whhT [H][4H] --------------------
// grid (32, 8), block (32, 8)
__global__ void k_whhT(const float* __restrict__ w_hh) {
    __shared__ float tile[32][33];
    int gb = blockIdx.x * 32;   // gate-row base (0..1023)
    int kb = blockIdx.y * 32;   // k base (0..255)
    int tx = threadIdx.x, ty = threadIdx.y;
#pragma unroll
    for (int i = 0; i < 32; i += 8)
        tile[ty + i][tx] = w_hh[(size_t)(gb + ty + i) * H_ + kb + tx];
    __syncthreads();
#pragma unroll
    for (int i = 0; i < 32; i += 8)
        g_whhT[(size_t)(kb + ty + i) * (4 * H_) + gb + tx] = tile[tx][ty + i];
}

// ---------------- K1: fused degree + P -------------------------------------------
__global__ void k_degP(const float* __restrict__ shots, const float* __restrict__ node,
                       const float* __restrict__ gcn_w) {
    __shared__ float gw[FIN_ * FOUT_];
    int r0 = blockIdx.x * 8;
    int w  = (r0 / N_) % W_;            // rows bw-major: bw = b*W + w
    for (int i = threadIdx.x; i < FIN_ * FOUT_; i += 256)
        gw[i] = gcn_w[(size_t)w * FIN_ * FOUT_ + i];
    __syncthreads();
    int warp = threadIdx.x >> 5, lane = threadIdx.x & 31;
    int r = r0 + warp;
    const float4* p = (const float4*)(shots + (size_t)r * N_);
    float s = 0.f;
#pragma unroll
    for (int i = 0; i < 8; i++) {
        float4 v = p[lane + 32 * i];
        s += v.x + v.y + v.z + v.w;
    }
#pragma unroll
    for (int o = 16; o; o >>= 1) s += __shfl_xor_sync(0xffffffffu, s, o);
    float d = 1.0f / sqrtf(1.0f + s);
    if (lane == 0) g_deg[r] = d;

    float nv = node[(size_t)r * FIN_ + lane];
    float acc = 0.f;
#pragma unroll
    for (int f = 0; f < FIN_; f++) {
        float x = __shfl_sync(0xffffffffu, nv, f);
        acc += x * gw[f * FOUT_ + lane];
    }
    g_P[(size_t)r * FOUT_ + lane] = d * acc;
}

// ---------------- K3: xpart[kq] = shots[n, kq-chunk] @ P[kq-chunk, :] ----------
static constexpr int AS_ = 292;   // A_shT row stride (floats)
__global__ __launch_bounds__(64) void k_gcn(const float* __restrict__ shots) {
    __shared__ __align__(16) float AT[16 * AS_];   // [kk][f(row)]
    __shared__ __align__(16) float PS[16 * 32];    // [kk][col]
    int bw = blockIdx.x >> 3;
    int n0 = (blockIdx.x & 7) << 7;      // * 128
    int kq = blockIdx.y;
    int t = threadIdx.x;
    int tx = t & 3;
    int ty = t >> 2;
    const float* Abase = shots + (size_t)bw * N_ * N_;
    const float* Pbase = g_P + (size_t)bw * N_ * FOUT_;

    unsigned long long acc[4][8];
#pragma unroll
    for (int i = 0; i < 4; i++)
#pragma unroll
        for (int j = 0; j < 8; j++) acc[i][j] = 0ull;

    const int r8 = ty * 8;
    const int fr = r8 + ((r8 >> 5) << 2);

    for (int k0 = kq * 128; k0 < kq * 128 + 128; k0 += 16) {
#pragma unroll
        for (int i = 0; i < 8; i++) {
            int idx = t + 64 * i;
            int rr = idx >> 2, q = idx & 3;
            float4 v = *(const float4*)(Abase + (size_t)(n0 + rr) * N_ + k0 + 4 * q);
            int f = rr + ((rr >> 5) << 2);
            AT[(4 * q + 0) * AS_ + f] = v.x;
            AT[(4 * q + 1) * AS_ + f] = v.y;
            AT[(4 * q + 2) * AS_ + f] = v.z;
            AT[(4 * q + 3) * AS_ + f] = v.w;
        }
#pragma unroll
        for (int i = 0; i < 2; i++) {
            int idx = t + 64 * i;
            int kk = idx >> 3, c = idx & 7;
            *(float4*)&PS[kk * 32 + 4 * c] =
                *(const float4*)(Pbase + (size_t)(k0 + kk) * 32 + 4 * c);
        }
        __syncthreads();
#pragma unroll 4
        for (int kk = 0; kk < 16; kk++) {
            ulonglong2 aA = *(const ulonglong2*)&AT[kk * AS_ + fr];
            ulonglong2 aB = *(const ulonglong2*)&AT[kk * AS_ + fr + 4];
            float4 p0 = *(const float4*)&PS[kk * 32 + tx * 8];
            float4 p1 = *(const float4*)&PS[kk * 32 + tx * 8 + 4];
            unsigned long long ap[4];
            ap[0] = aA.x; ap[1] = aA.y; ap[2] = aB.x; ap[3] = aB.y;
            unsigned long long bb[8];
            PACK2(bb[0], p0.x); PACK2(bb[1], p0.y); PACK2(bb[2], p0.z); PACK2(bb[3], p0.w);
            PACK2(bb[4], p1.x); PACK2(bb[5], p1.y); PACK2(bb[6], p1.z); PACK2(bb[7], p1.w);
#pragma unroll
            for (int i = 0; i < 4; i++)
#pragma unroll
                for (int j = 0; j < 8; j++) FMA2(acc[i][j], ap[i], bb[j]);
        }
        __syncthreads();
    }

    float* Xp = g_xpart + (size_t)kq * BW_ * N_ * FOUT_ + (size_t)bw * N_ * FOUT_;
#pragma unroll
    for (int i = 0; i < 4; i++) {
        int ne = n0 + r8 + 2 * i;
        float lo[8], hi[8];
#pragma unroll
        for (int j = 0; j < 8; j++) UNPACK2(lo[j], hi[j], acc[i][j]);
        float4 o0 = {lo[0], lo[1], lo[2], lo[3]};
        float4 o1 = {lo[4], lo[5], lo[6], lo[7]};
        float4 o2 = {hi[0], hi[1], hi[2], hi[3]};
        float4 o3 = {hi[4], hi[5], hi[6], hi[7]};
        *(float4*)(Xp + (size_t)ne * 32 + tx * 8) = o0;
        *(float4*)(Xp + (size_t)ne * 32 + tx * 8 + 4) = o1;
        *(float4*)(Xp + (size_t)(ne + 1) * 32 + tx * 8) = o2;
        *(float4*)(Xp + (size_t)(ne + 1) * 32 + tx * 8 + 4) = o3;
    }
}

// ---------------- K3f: XT[k][wb] = d[n]*(sum_kq xpart + P), smem-tiled transpose -
__global__ void k_xfin(void) {
    __shared__ float tile[128 * 49];   // [rr][wb'] (stride 49: conflict-free)
    int rt = blockIdx.x * 128;
    int t = threadIdx.x;
#pragma unroll 4
    for (int pass = 0; pass < 24; pass++) {
        int p = pass * 256 + t;
        int bw = p >> 7, rr = p & 127;
        int r = rt + rr;
        float s = g_P[(size_t)bw * D_ + r];
#pragma unroll
        for (int kq = 0; kq < KQ_; kq++)
            s += g_xpart[(size_t)kq * BW_ * D_ + (size_t)bw * D_ + r];
        s *= g_deg[bw * N_ + (r >> 5)];
        int w = bw % W_, b = bw / W_;
        tile[rr * 49 + (w * B_ + b)] = s;
    }
    __syncthreads();
#pragma unroll 4
    for (int pass = 0; pass < 24; pass++) {
        int o = pass * 256 + t;
        int rr = o / 48, c = o % 48;
        g_XT[(size_t)(rt + rr) * BW_ + c] = tile[rr * 49 + c];
    }
}

// ---------------- K4: gates_x = X @ w_ih^T  (dual cp.async, 4 blocks/SM) --------
static constexpr int WROW_ = 36;                  // W smem row stride (floats)
static constexpr int WBUF_ = 128 * WROW_;         // 4608 floats per buffer
static constexpr int XS_   = 52;                  // XT smem row stride
static constexpr int XBUF_ = 32 * XS_;            // 1664 floats per buffer
static constexpr int GATES_SMEM = (2 * WBUF_ + 2 * XBUF_) * 4;   // 50176 B

__global__ __launch_bounds__(192, 4) void k_gates(const float* __restrict__ w_ih) {
    extern __shared__ __align__(16) float sm[];
    float* WS = sm;                 // [2][128][36]
    float* XT = sm + 2 * WBUF_;     // [2][32][52]
    const int g0 = blockIdx.x * 128;
    const int kc = blockIdx.y;
    const int kbase = kc * 512;
    const int t = threadIdx.x;
    const int warp = t >> 5, gl = t & 31;
    const int wb0 = warp * 8;
    const uint32_t ws_smem = (uint32_t)__cvta_generic_to_shared(WS);
    const uint32_t xt_smem = (uint32_t)__cvta_generic_to_shared(XT);

    unsigned long long acc[4][4];
#pragma unroll
    for (int i = 0; i < 4; i++)
#pragma unroll
        for (int j = 0; j < 4; j++) acc[i][j] = 0ull;

#define STAGE(bufi, k0)                                                            \
    do {                                                                           \
        for (int idx = t; idx < 1024; idx += 192) {                                \
            int g = idx >> 3, q = idx & 7;                                         \
            cp16(ws_smem + ((bufi) * WBUF_ + g * WROW_ + 4 * q) * 4,               \
                 w_ih + (size_t)(g0 + g) * D_ + (k0) + 4 * q);                     \
        }                                                                          \
        for (int idx = t; idx < 384; idx += 192) {                                 \
            int kk = idx / 12, q = idx % 12;                                       \
            cp16(xt_smem + ((bufi) * XBUF_ + kk * XS_ + 4 * q) * 4,                \
                 g_XT + (size_t)((k0) + kk) * BW_ + 4 * q);                        \
        }                                                                          \
        CP_COMMIT();                                                               \
    } while (0)

    STAGE(0, kbase);

    for (int s = 0; s < 16; s++) {
        int buf = s & 1;
        __syncthreads();   // previous compute done -> other buffer free
        if (s < 15) {
            STAGE(buf ^ 1, kbase + 32 * (s + 1));
            CP_WAIT1();
        } else {
            CP_WAIT0();
        }
        __syncthreads();
        const float* WB = WS + buf * WBUF_;
        const float* XB = XT + buf * XBUF_;
#pragma unroll
        for (int kkc = 0; kkc < 8; kkc++) {
            unsigned long long ap[4][4];
#pragma unroll
            for (int kk = 0; kk < 4; kk++) {
                int krow = kkc * 4 + kk;
                ulonglong2 xA = *(const ulonglong2*)&XB[krow * XS_ + wb0];
                ulonglong2 xB2 = *(const ulonglong2*)&XB[krow * XS_ + wb0 + 4];
                ap[kk][0] = xA.x; ap[kk][1] = xA.y; ap[kk][2] = xB2.x; ap[kk][3] = xB2.y;
            }
#pragma unroll
            for (int j = 0; j < 4; j++) {
                float4 v = *(const float4*)&WB[(gl + 32 * j) * WROW_ + kkc * 4];
                float wf[4] = {v.x, v.y, v.z, v.w};
#pragma unroll
                for (int kk = 0; kk < 4; kk++) {
                    unsigned long long b2;
                    PACK2(b2, wf[kk]);
#pragma unroll
                    for (int i = 0; i < 4; i++) FMA2(acc[i][j], ap[kk][i], b2);
                }
            }
        }
    }
#undef STAGE

    // epilogue -> split-K partials
#pragma unroll
    for (int i = 0; i < 4; i++) {
#pragma unroll
        for (int j = 0; j < 4; j++) {
            float lo, hi;
            UNPACK2(lo, hi, acc[i][j]);
            int gcol = g0 + gl + 32 * j;
            g_part[((size_t)kc * BW_ + wb0 + 2 * i) * 1024 + gcol] = lo;
            g_part[((size_t)kc * BW_ + wb0 + 2 * i + 1) * 1024 + gcol] = hi;
        }
    }
}

// ---------------- K4r: reduce split-K + biases ----------------------------------
__global__ void k_greduce(const float* __restrict__ b_ih, const float* __restrict__ b_hh) {
    int i = blockIdx.x * 256 + threadIdx.x;   // 0..49151
    int g = i & 1023;
    float s = b_ih[g] + b_hh[g];
#pragma unroll 8
    for (int kc = 0; kc < KC_; kc++) s += g_part[(size_t)kc * BW_ * 1024 + i];
    g_gates[i] = s;
}

// ---------------- K5: fused 12-step LSTM (one block per batch, coalesced whhT) --
// grid B_ x 256 threads; thread = hidden unit j; h double-buffered in smem.
// whhT[k][g]: lanes j consecutive -> coalesced loads (1 line / warp-load).
__global__ __launch_bounds__(256) void k_lstm() {
    __shared__ __align__(16) float hsh[2][H_];
    int b = blockIdx.x;
    int j = threadIdx.x;
    float cc = 0.f;
    hsh[0][j] = 0.f;
    __syncthreads();

    for (int w = 0; w < W_; w++) {
        int p = w & 1;
        const float* gx = g_gates + ((size_t)(w * B_ + b)) * 4 * H_;
        float a0 = gx[j], a1 = gx[H_ + j], a2 = gx[2 * H_ + j], a3 = gx[3 * H_ + j];
#pragma unroll 8
        for (int k = 0; k < H_; k++) {
            float hk = hsh[p][k];
            const float* wr = g_whhT + (size_t)k * (4 * H_);
            a0 += wr[j] * hk;
            a1 += wr[H_ + j] * hk;
            a2 += wr[2 * H_ + j] * hk;
            a3 += wr[3 * H_ + j] * hk;
        }
        float ig = 1.0f / (1.0f + expf(-a0));
        float fg = 1.0f / (1.0f + expf(-a1));
        float gg = tanhf(a2);
        float og = 1.0f / (1.0f + expf(-a3));
        cc = fg * cc + ig * gg;
        hsh[p ^ 1][j] = og * tanhf(cc);
        __syncthreads();
    }
    g_hn[b * H_ + j] = hsh[0][j];   // after 12 steps result is in buffer 0
}

// ---------------- K6: out[b, r] = hn[b,:]·f1_w[r,:] + f1_b[r] -------------------
__global__ void k_out(const float* __restrict__ f1_w, const float* __restrict__ f1_b) {
    __shared__ __align__(16) float hsh[B_ * H_];
    for (int i = threadIdx.x; i < B_ * H_; i += 256) hsh[i] = g_hn[i];
    __syncthreads();
    int warp = threadIdx.x >> 5, lane = threadIdx.x & 31;
    int r = blockIdx.x * 8 + warp;
    const float4* Wr = (const float4*)(f1_w + (size_t)r * H_);
    float a[B_] = {0.f, 0.f, 0.f, 0.f};
#pragma unroll
    for (int t = 0; t < 2; t++) {
        int idx = lane + 32 * t;
        float4 wv = Wr[idx];
#pragma unroll
        for (int b = 0; b < B_; b++) {
            float4 hv = *(const float4*)&hsh[b * H_ + idx * 4];
            a[b] += wv.x * hv.x + wv.y * hv.y + wv.z * hv.z + wv.w * hv.w;
        }
    }
#pragma unroll
    for (int b = 0; b < B_; b++) {
#pragma unroll
        for (int o = 16; o; o >>= 1) a[b] += __shfl_xor_sync(0xffffffffu, a[b], o);
    }
    if (lane == 0) {
        float bb = f1_b[r];
#pragma unroll
        for (int b = 0; b < B_; b++) g_out[(size_t)b * D_ + r] = a[b] + bb;
    }
}

// ---------------- K6c: s1[b,n], s2[b,n] -----------------------------------------
__global__ void k_s(const float* __restrict__ f2_w) {
    int idx = blockIdx.x * 256 + threadIdx.x;
    const float4* v4 = (const float4*)(g_out + (size_t)idx * FOUT_);
    const float4* w1 = (const float4*)(f2_w);
    const float4* w2 = (const float4*)(f2_w + FOUT_);
    float s1 = 0.f, s2 = 0.f;
#pragma unroll
    for (int t = 0; t < 8; t++) {
        float4 v = v4[t], a = w1[t], b = w2[t];
        s1 += v.x * a.x + v.y * a.y + v.z * a.z + v.w * a.w;
        s2 += v.x * b.x + v.y * b.y + v.z * b.z + v.w * b.w;
    }
    g_s1[idx] = s1;
    g_s2[idx] = s2;
}

// ---------------- K7: scores, keep mask, L1 row-normalize, write output ----------
__global__ void k_final(float* __restrict__ res, const float* __restrict__ f2_b) {
    __shared__ float s1s[N_], s2s[N_];
    __shared__ float wsum[8];
    __shared__ float total;
    int b = blockIdx.x >> 10;
    int i = blockIdx.x & 1023;
    for (int t = threadIdx.x; t < N_; t += 256) {
        s1s[t] = g_s1[b * N_ + t];
        s2s[t] = g_s2[b * N_ + t];
    }
    __syncthreads();
    float bias = f2_b[0];
    float s1i = s1s[i], s2i = s2s[i];
    float v[4];
    float asum = 0.f;
#pragma unroll
    for (int t = 0; t < 4; t++) {
        int j = threadIdx.x + t * 256;
        float sc = s1i + s2s[j] + bias;
        float st = s1s[j] + s2i + bias;
        float val;
        if (i == j) {
            val = sc;
        } else {
            bool keep = (i < j) ? (sc >= st && sc > 0.f) : (sc > st && sc >= 0.f);
            val = keep ? sc : 0.f;
        }
        v[t] = val;
        asum += fabsf(val);
    }
    int warp = threadIdx.x >> 5, lane = threadIdx.x & 31;
#pragma unroll
    for (int o = 16; o; o >>= 1) asum += __shfl_xor_sync(0xffffffffu, asum, o);
    if (lane == 0) wsum[warp] = asum;
    __syncthreads();
    if (threadIdx.x == 0) {
        float s = 0.f;
#pragma unroll
        for (int k = 0; k < 8; k++) s += wsum[k];
        total = s;
    }
    __syncthreads();
    float inv = 1.0f / fmaxf(total, 1e-12f);
    float* row = res + ((size_t)b * N_ + i) * N_;
#pragma unroll
    for (int t = 0; t < 4; t++) row[threadIdx.x + t * 256] = v[t] * inv;
}

// =================================================================================
extern "C" void kernel_launch(void* const* d_in, const int* in_sizes, int n_in,
                              void* d_out, int out_size) {
    const float* shots = (const float*)d_in[0];
    const float* node  = (const float*)d_in[1];
    // d_in[2] = 'a' (unused by reference)
    const float* gcn_w = (const float*)d_in[3];
    const float* w_ih  = (const float*)d_in[4];
    const float* w_hh  = (const float*)d_in[5];
    const float* b_ih  = (const float*)d_in[6];
    const float* b_hh  = (const float*)d_in[7];
    const float* f1_w  = (const float*)d_in[8];
    const float* f1_b  = (const float*)d_in[9];
    const float* f2_w  = (const float*)d_in[10];
    const float* f2_b  = (const float*)d_in[11];
    float* res = (float*)d_out;

    cudaFuncSetAttribute(k_gates, cudaFuncAttributeMaxDynamicSharedMemorySize, GATES_SMEM);

    k_whhT<<<dim3(32, 8), dim3(32, 8)>>>(w_hh);          // #1 (independent)
    k_degP<<<BW_ * N_ / 8, 256>>>(shots, node, gcn_w);   // #2
    k_gcn<<<dim3(BW_ * 8, KQ_), 64>>>(shots);            // #3
    k_xfin<<<D_ / 128, 256>>>();                         // #4
    k_gates<<<dim3(8, KC_), 192, GATES_SMEM>>>(w_ih);    // #5
    k_greduce<<<BW_ * 4 * H_ / 256, 256>>>(b_ih, b_hh);  // #6
    k_lstm<<<B_, H_>>>();                                // #7
    k_out<<<D_ / 8, 256>>>(f1_w, f1_b);                  // #8
    k_s<<<B_ * N_ / 256, 256>>>(f2_w);                   // #9
    k_final<<<B_ * N_, 256>>>(res, f2_b);                // #10
}

// round 12
// speedup vs baseline: 2.1008x; 1.0322x over previous
#include <cuda_runtime.h>
#include <cstdint>

// Problem constants
static constexpr int B_   = 4;
static constexpr int W_   = 12;
static constexpr int N_   = 1024;
static constexpr int FIN_ = 32;
static constexpr int FOUT_= 32;
static constexpr int H_   = 256;
static constexpr int BW_  = B_ * W_;        // 48
static constexpr int D_   = N_ * FOUT_;     // 32768
static constexpr int KC_  = 64;             // split-K chunks for gates GEMM (k=512 each)
static constexpr int KQ_  = 8;              // split-K for gcn GEMM (k=128 each)

// ---------------- packed f32x2 helpers ----------------
#define FMA2(acc, a, b) asm("fma.rn.f32x2 %0, %1, %2, %0;" : "+l"(acc) : "l"(a), "l"(b))
#define PACK2(d, f)     asm("mov.b64 %0, {%1, %1};" : "=l"(d) : "f"(f))
#define UNPACK2(lo, hi, d) asm("mov.b64 {%0, %1}, %2;" : "=f"(lo), "=f"(hi) : "l"(d))

// ---------------- cp.async helpers ----------------
__device__ __forceinline__ void cp16(uint32_t dst, const void* src) {
    asm volatile("cp.async.cg.shared.global [%0], [%1], 16;" :: "r"(dst), "l"(src));
}
#define CP_COMMIT() asm volatile("cp.async.commit_group;")
#define CP_WAIT1()  asm volatile("cp.async.wait_group 1;")
#define CP_WAIT0()  asm volatile("cp.async.wait_group 0;")

// ---------------- scratch (static device globals; no allocation) ----------------
__device__ float g_deg[BW_ * N_];
__device__ float g_P[(size_t)BW_ * N_ * FOUT_];
__device__ float g_xpart[(size_t)KQ_ * BW_ * N_ * FOUT_];   // gcn split-K partials
__device__ float g_XT[(size_t)D_ * BW_];                    // X transposed: [k][wb]
__device__ float g_part[(size_t)KC_ * BW_ * 4 * H_];        // gates split-K partials
__device__ float g_gates[BW_ * 4 * H_];
__device__ float g_whhT[(size_t)H_ * 4 * H_];               // [k][j*4+r] interleaved
__device__ float g_hn[B_ * H_];
__device__ float g_out[B_ * D_];
__device__ float g_s1[B_ * N_];
__device__ float g_s2[B_ * N_];

// ---------------- K0: transpose w_hh [4H][H] -> whhT [k][j*4+r] -----------------
// grid (32, 8), block (32, 8)
__global__ void k_whhT(const float* __restrict__ w_hh) {
    __shared__ float tile[32][33];
    int gb = blockIdx.x * 32;   // gate-row base (0..1023), never crosses 256 bnd
    int kb = blockIdx.y * 32;   // k base (0..255)
    int tx = threadIdx.x, ty = threadIdx.y;
#pragma unroll
    for (int i = 0; i < 32; i += 8)
        tile[ty + i][tx] = w_hh[(size_t)(gb + ty + i) * H_ + kb + tx];
    __syncthreads();
    int r = gb >> 8;            // gate index (0..3), same for all tx
    int jb = gb & 255;          // unit base
#pragma unroll
    for (int i = 0; i < 32; i += 8)
        g_whhT[(size_t)(kb + ty + i) * (4 * H_) + (jb + tx) * 4 + r] = tile[tx][ty + i];
}

// ---------------- K1: fused degree + P -------------------------------------------
__global__ void k_degP(const float* __restrict__ shots, const float* __restrict__ node,
                       const float* __restrict__ gcn_w) {
    __shared__ float gw[FIN_ * FOUT_];
    int r0 = blockIdx.x * 8;
    int w  = (r0 / N_) % W_;            // rows bw-major: bw = b*W + w
    for (int i = threadIdx.x; i < FIN_ * FOUT_; i += 256)
        gw[i] = gcn_w[(size_t)w * FIN_ * FOUT_ + i];
    __syncthreads();
    int warp = threadIdx.x >> 5, lane = threadIdx.x & 31;
    int r = r0 + warp;
    const float4* p = (const float4*)(shots + (size_t)r * N_);
    float s = 0.f;
#pragma unroll
    for (int i = 0; i < 8; i++) {
        float4 v = p[lane + 32 * i];
        s += v.x + v.y + v.z + v.w;
    }
#pragma unroll
    for (int o = 16; o; o >>= 1) s += __shfl_xor_sync(0xffffffffu, s, o);
    float d = 1.0f / sqrtf(1.0f + s);
    if (lane == 0) g_deg[r] = d;

    float nv = node[(size_t)r * FIN_ + lane];
    float acc = 0.f;
#pragma unroll
    for (int f = 0; f < FIN_; f++) {
        float x = __shfl_sync(0xffffffffu, nv, f);
        acc += x * gw[f * FOUT_ + lane];
    }
    g_P[(size_t)r * FOUT_ + lane] = d * acc;
}

// ---------------- K3: xpart[kq] = shots[n, kq-chunk] @ P[kq-chunk, :] ----------
static constexpr int AS_ = 292;   // A_shT row stride (floats)
__global__ __launch_bounds__(64) void k_gcn(const float* __restrict__ shots) {
    __shared__ __align__(16) float AT[16 * AS_];   // [kk][f(row)]
    __shared__ __align__(16) float PS[16 * 32];    // [kk][col]
    int bw = blockIdx.x >> 3;
    int n0 = (blockIdx.x & 7) << 7;      // * 128
    int kq = blockIdx.y;
    int t = threadIdx.x;
    int tx = t & 3;
    int ty = t >> 2;
    const float* Abase = shots + (size_t)bw * N_ * N_;
    const float* Pbase = g_P + (size_t)bw * N_ * FOUT_;

    unsigned long long acc[4][8];
#pragma unroll
    for (int i = 0; i < 4; i++)
#pragma unroll
        for (int j = 0; j < 8; j++) acc[i][j] = 0ull;

    const int r8 = ty * 8;
    const int fr = r8 + ((r8 >> 5) << 2);

    for (int k0 = kq * 128; k0 < kq * 128 + 128; k0 += 16) {
#pragma unroll
        for (int i = 0; i < 8; i++) {
            int idx = t + 64 * i;
            int rr = idx >> 2, q = idx & 3;
            float4 v = *(const float4*)(Abase + (size_t)(n0 + rr) * N_ + k0 + 4 * q);
            int f = rr + ((rr >> 5) << 2);
            AT[(4 * q + 0) * AS_ + f] = v.x;
            AT[(4 * q + 1) * AS_ + f] = v.y;
            AT[(4 * q + 2) * AS_ + f] = v.z;
            AT[(4 * q + 3) * AS_ + f] = v.w;
        }
#pragma unroll
        for (int i = 0; i < 2; i++) {
            int idx = t + 64 * i;
            int kk = idx >> 3, c = idx & 7;
            *(float4*)&PS[kk * 32 + 4 * c] =
                *(const float4*)(Pbase + (size_t)(k0 + kk) * 32 + 4 * c);
        }
        __syncthreads();
#pragma unroll 4
        for (int kk = 0; kk < 16; kk++) {
            ulonglong2 aA = *(const ulonglong2*)&AT[kk * AS_ + fr];
            ulonglong2 aB = *(const ulonglong2*)&AT[kk * AS_ + fr + 4];
            float4 p0 = *(const float4*)&PS[kk * 32 + tx * 8];
            float4 p1 = *(const float4*)&PS[kk * 32 + tx * 8 + 4];
            unsigned long long ap[4];
            ap[0] = aA.x; ap[1] = aA.y; ap[2] = aB.x; ap[3] = aB.y;
            unsigned long long bb[8];
            PACK2(bb[0], p0.x); PACK2(bb[1], p0.y); PACK2(bb[2], p0.z); PACK2(bb[3], p0.w);
            PACK2(bb[4], p1.x); PACK2(bb[5], p1.y); PACK2(bb[6], p1.z); PACK2(bb[7], p1.w);
#pragma unroll
            for (int i = 0; i < 4; i++)
#pragma unroll
                for (int j = 0; j < 8; j++) FMA2(acc[i][j], ap[i], bb[j]);
        }
        __syncthreads();
    }

    float* Xp = g_xpart + (size_t)kq * BW_ * N_ * FOUT_ + (size_t)bw * N_ * FOUT_;
#pragma unroll
    for (int i = 0; i < 4; i++) {
        int ne = n0 + r8 + 2 * i;
        float lo[8], hi[8];
#pragma unroll
        for (int j = 0; j < 8; j++) UNPACK2(lo[j], hi[j], acc[i][j]);
        float4 o0 = {lo[0], lo[1], lo[2], lo[3]};
        float4 o1 = {lo[4], lo[5], lo[6], lo[7]};
        float4 o2 = {hi[0], hi[1], hi[2], hi[3]};
        float4 o3 = {hi[4], hi[5], hi[6], hi[7]};
        *(float4*)(Xp + (size_t)ne * 32 + tx * 8) = o0;
        *(float4*)(Xp + (size_t)ne * 32 + tx * 8 + 4) = o1;
        *(float4*)(Xp + (size_t)(ne + 1) * 32 + tx * 8) = o2;
        *(float4*)(Xp + (size_t)(ne + 1) * 32 + tx * 8 + 4) = o3;
    }
}

// ---------------- K3f: XT[k][wb] = d[n]*(sum_kq xpart + P), smem-tiled transpose -
// 512 blocks x 256 thr; block handles 64 consecutive k-rows (more blocks/SM).
__global__ void k_xfin(void) {
    __shared__ float tile[64 * 49];    // [rr][wb'] (stride 49: conflict-free)
    int rt = blockIdx.x * 64;
    int t = threadIdx.x;
#pragma unroll 4
    for (int pass = 0; pass < 12; pass++) {
        int p = pass * 256 + t;
        int bw = p >> 6, rr = p & 63;
        int r = rt + rr;
        float s = g_P[(size_t)bw * D_ + r];
#pragma unroll
        for (int kq = 0; kq < KQ_; kq++)
            s += g_xpart[(size_t)kq * BW_ * D_ + (size_t)bw * D_ + r];
        s *= g_deg[bw * N_ + (r >> 5)];
        int w = bw % W_, b = bw / W_;
        tile[rr * 49 + (w * B_ + b)] = s;
    }
    __syncthreads();
#pragma unroll 4
    for (int pass = 0; pass < 12; pass++) {
        int o = pass * 256 + t;
        int rr = o / 48, c = o % 48;
        g_XT[(size_t)(rt + rr) * BW_ + c] = tile[rr * 49 + c];
    }
}

// ---------------- K4: gates_x = X @ w_ih^T  (dual cp.async, 4 blocks/SM) --------
static constexpr int WROW_ = 36;                  // W smem row stride (floats)
static constexpr int WBUF_ = 128 * WROW_;         // 4608 floats per buffer
static constexpr int XS_   = 52;                  // XT smem row stride
static constexpr int XBUF_ = 32 * XS_;            // 1664 floats per buffer
static constexpr int GATES_SMEM = (2 * WBUF_ + 2 * XBUF_) * 4;   // 50176 B

__global__ __launch_bounds__(192, 4) void k_gates(const float* __restrict__ w_ih) {
    extern __shared__ __align__(16) float sm[];
    float* WS = sm;                 // [2][128][36]
    float* XT = sm + 2 * WBUF_;     // [2][32][52]
    const int g0 = blockIdx.x * 128;
    const int kc = blockIdx.y;
    const int kbase = kc * 512;
    const int t = threadIdx.x;
    const int warp = t >> 5, gl = t & 31;
    const int wb0 = warp * 8;
    const uint32_t ws_smem = (uint32_t)__cvta_generic_to_shared(WS);
    const uint32_t xt_smem = (uint32_t)__cvta_generic_to_shared(XT);

    unsigned long long acc[4][4];
#pragma unroll
    for (int i = 0; i < 4; i++)
#pragma unroll
        for (int j = 0; j < 4; j++) acc[i][j] = 0ull;

#define STAGE(bufi, k0)                                                            \
    do {                                                                           \
        for (int idx = t; idx < 1024; idx += 192) {                                \
            int g = idx >> 3, q = idx & 7;                                         \
            cp16(ws_smem + ((bufi) * WBUF_ + g * WROW_ + 4 * q) * 4,               \
                 w_ih + (size_t)(g0 + g) * D_ + (k0) + 4 * q);                     \
        }                                                                          \
        for (int idx = t; idx < 384; idx += 192) {                                 \
            int kk = idx / 12, q = idx % 12;                                       \
            cp16(xt_smem + ((bufi) * XBUF_ + kk * XS_ + 4 * q) * 4,                \
                 g_XT + (size_t)((k0) + kk) * BW_ + 4 * q);                        \
        }                                                                          \
        CP_COMMIT();                                                               \
    } while (0)

    STAGE(0, kbase);

    for (int s = 0; s < 16; s++) {
        int buf = s & 1;
        __syncthreads();   // previous compute done -> other buffer free
        if (s < 15) {
            STAGE(buf ^ 1, kbase + 32 * (s + 1));
            CP_WAIT1();
        } else {
            CP_WAIT0();
        }
        __syncthreads();
        const float* WB = WS + buf * WBUF_;
        const float* XB = XT + buf * XBUF_;
#pragma unroll
        for (int kkc = 0; kkc < 8; kkc++) {
            unsigned long long ap[4][4];
#pragma unroll
            for (int kk = 0; kk < 4; kk++) {
                int krow = kkc * 4 + kk;
                ulonglong2 xA = *(const ulonglong2*)&XB[krow * XS_ + wb0];
                ulonglong2 xB2 = *(const ulonglong2*)&XB[krow * XS_ + wb0 + 4];
                ap[kk][0] = xA.x; ap[kk][1] = xA.y; ap[kk][2] = xB2.x; ap[kk][3] = xB2.y;
            }
#pragma unroll
            for (int j = 0; j < 4; j++) {
                float4 v = *(const float4*)&WB[(gl + 32 * j) * WROW_ + kkc * 4];
                float wf[4] = {v.x, v.y, v.z, v.w};
#pragma unroll
                for (int kk = 0; kk < 4; kk++) {
                    unsigned long long b2;
                    PACK2(b2, wf[kk]);
#pragma unroll
                    for (int i = 0; i < 4; i++) FMA2(acc[i][j], ap[kk][i], b2);
                }
            }
        }
    }
#undef STAGE

    // epilogue -> split-K partials
#pragma unroll
    for (int i = 0; i < 4; i++) {
#pragma unroll
        for (int j = 0; j < 4; j++) {
            float lo, hi;
            UNPACK2(lo, hi, acc[i][j]);
            int gcol = g0 + gl + 32 * j;
            g_part[((size_t)kc * BW_ + wb0 + 2 * i) * 1024 + gcol] = lo;
            g_part[((size_t)kc * BW_ + wb0 + 2 * i + 1) * 1024 + gcol] = hi;
        }
    }
}

// ---------------- K4r: reduce split-K + biases ----------------------------------
__global__ void k_greduce(const float* __restrict__ b_ih, const float* __restrict__ b_hh) {
    int i = blockIdx.x * 256 + threadIdx.x;   // 0..49151
    int g = i & 1023;
    float s = b_ih[g] + b_hh[g];
#pragma unroll 8
    for (int kc = 0; kc < KC_; kc++) s += g_part[(size_t)kc * BW_ * 1024 + i];
    g_gates[i] = s;
}

// ---------------- K5: fused 12-step LSTM (1 block/batch, LDG.128 weights) -------
// grid B_ x 256 threads; thread = hidden unit j. Interleaved whhT gives all 4
// gate weights for unit j in one float4 -> 1 LDG.128 per k per thread.
__global__ __launch_bounds__(256) void k_lstm() {
    __shared__ __align__(16) float hsh[2][H_];
    int b = blockIdx.x;
    int j = threadIdx.x;
    float cc = 0.f;
    hsh[0][j] = 0.f;
    __syncthreads();
    const float4* w4 = (const float4*)g_whhT;   // [k][j] float4 = gates i,f,g,o

    for (int w = 0; w < W_; w++) {
        int p = w & 1;
        const float* gx = g_gates + ((size_t)(w * B_ + b)) * 4 * H_;
        float a0 = gx[j], a1 = gx[H_ + j], a2 = gx[2 * H_ + j], a3 = gx[3 * H_ + j];
#pragma unroll 8
        for (int k = 0; k < H_; k++) {
            float hk = hsh[p][k];
            float4 wv = w4[(size_t)k * H_ + j];
            a0 += wv.x * hk;
            a1 += wv.y * hk;
            a2 += wv.z * hk;
            a3 += wv.w * hk;
        }
        float ig = 1.0f / (1.0f + expf(-a0));
        float fg = 1.0f / (1.0f + expf(-a1));
        float gg = tanhf(a2);
        float og = 1.0f / (1.0f + expf(-a3));
        cc = fg * cc + ig * gg;
        hsh[p ^ 1][j] = og * tanhf(cc);
        __syncthreads();
    }
    g_hn[b * H_ + j] = hsh[0][j];   // after 12 steps result is in buffer 0
}

// ---------------- K6: out[b, r] = hn[b,:]·f1_w[r,:] + f1_b[r] -------------------
__global__ void k_out(const float* __restrict__ f1_w, const float* __restrict__ f1_b) {
    __shared__ __align__(16) float hsh[B_ * H_];
    for (int i = threadIdx.x; i < B_ * H_; i += 256) hsh[i] = g_hn[i];
    __syncthreads();
    int warp = threadIdx.x >> 5, lane = threadIdx.x & 31;
    int r = blockIdx.x * 8 + warp;
    const float4* Wr = (const float4*)(f1_w + (size_t)r * H_);
    float a[B_] = {0.f, 0.f, 0.f, 0.f};
#pragma unroll
    for (int t = 0; t < 2; t++) {
        int idx = lane + 32 * t;
        float4 wv = Wr[idx];
#pragma unroll
        for (int b = 0; b < B_; b++) {
            float4 hv = *(const float4*)&hsh[b * H_ + idx * 4];
            a[b] += wv.x * hv.x + wv.y * hv.y + wv.z * hv.z + wv.w * hv.w;
        }
    }
#pragma unroll
    for (int b = 0; b < B_; b++) {
#pragma unroll
        for (int o = 16; o; o >>= 1) a[b] += __shfl_xor_sync(0xffffffffu, a[b], o);
    }
    if (lane == 0) {
        float bb = f1_b[r];
#pragma unroll
        for (int b = 0; b < B_; b++) g_out[(size_t)b * D_ + r] = a[b] + bb;
    }
}

// ---------------- K6c: s1[b,n], s2[b,n] -----------------------------------------
__global__ void k_s(const float* __restrict__ f2_w) {
    int idx = blockIdx.x * 256 + threadIdx.x;
    const float4* v4 = (const float4*)(g_out + (size_t)idx * FOUT_);
    const float4* w1 = (const float4*)(f2_w);
    const float4* w2 = (const float4*)(f2_w + FOUT_);
    float s1 = 0.f, s2 = 0.f;
#pragma unroll
    for (int t = 0; t < 8; t++) {
        float4 v = v4[t], a = w1[t], b = w2[t];
        s1 += v.x * a.x + v.y * a.y + v.z * a.z + v.w * a.w;
        s2 += v.x * b.x + v.y * b.y + v.z * b.z + v.w * b.w;
    }
    g_s1[idx] = s1;
    g_s2[idx] = s2;
}

// ---------------- K7: scores, keep mask, L1 row-normalize, write output ----------
__global__ void k_final(float* __restrict__ res, const float* __restrict__ f2_b) {
    __shared__ float s1s[N_], s2s[N_];
    __shared__ float wsum[8];
    __shared__ float total;
    int b = blockIdx.x >> 10;
    int i = blockIdx.x & 1023;
    for (int t = threadIdx.x; t < N_; t += 256) {
        s1s[t] = g_s1[b * N_ + t];
        s2s[t] = g_s2[b * N_ + t];
    }
    __syncthreads();
    float bias = f2_b[0];
    float s1i = s1s[i], s2i = s2s[i];
    float v[4];
    float asum = 0.f;
#pragma unroll
    for (int t = 0; t < 4; t++) {
        int j = threadIdx.x + t * 256;
        float sc = s1i + s2s[j] + bias;
        float st = s1s[j] + s2i + bias;
        float val;
        if (i == j) {
            val = sc;
        } else {
            bool keep = (i < j) ? (sc >= st && sc > 0.f) : (sc > st && sc >= 0.f);
            val = keep ? sc : 0.f;
        }
        v[t] = val;
        asum += fabsf(val);
    }
    int warp = threadIdx.x >> 5, lane = threadIdx.x & 31;
#pragma unroll
    for (int o = 16; o; o >>= 1) asum += __shfl_xor_sync(0xffffffffu, asum, o);
    if (lane == 0) wsum[warp] = asum;
    __syncthreads();
    if (threadIdx.x == 0) {
        float s = 0.f;
#pragma unroll
        for (int k = 0; k < 8; k++) s += wsum[k];
        total = s;
    }
    __syncthreads();
    float inv = 1.0f / fmaxf(total, 1e-12f);
    float* row = res + ((size_t)b * N_ + i) * N_;
#pragma unroll
    for (int t = 0; t < 4; t++) row[threadIdx.x + t * 256] = v[t] * inv;
}

// =================================================================================
extern "C" void kernel_launch(void* const* d_in, const int* in_sizes, int n_in,
                              void* d_out, int out_size) {
    const float* shots = (const float*)d_in[0];
    const float* node  = (const float*)d_in[1];
    // d_in[2] = 'a' (unused by reference)
    const float* gcn_w = (const float*)d_in[3];
    const float* w_ih  = (const float*)d_in[4];
    const float* w_hh  = (const float*)d_in[5];
    const float* b_ih  = (const float*)d_in[6];
    const float* b_hh  = (const float*)d_in[7];
    const float* f1_w  = (const float*)d_in[8];
    const float* f1_b  = (const float*)d_in[9];
    const float* f2_w  = (const float*)d_in[10];
    const float* f2_b  = (const float*)d_in[11];
    float* res = (float*)d_out;

    cudaFuncSetAttribute(k_gates, cudaFuncAttributeMaxDynamicSharedMemorySize, GATES_SMEM);

    k_whhT<<<dim3(32, 8), dim3(32, 8)>>>(w_hh);          // #1 (independent)
    k_degP<<<BW_ * N_ / 8, 256>>>(shots, node, gcn_w);   // #2
    k_gcn<<<dim3(BW_ * 8, KQ_), 64>>>(shots);            // #3
    k_xfin<<<D_ / 64, 256>>>();                          // #4
    k_gates<<<dim3(8, KC_), 192, GATES_SMEM>>>(w_ih);    // #5
    k_greduce<<<BW_ * 4 * H_ / 256, 256>>>(b_ih, b_hh);  // #6
    k_lstm<<<B_, H_>>>();                                // #7
    k_out<<<D_ / 8, 256>>>(f1_w, f1_b);                  // #8
    k_s<<<B_ * N_ / 256, 256>>>(f2_w);                   // #9
    k_final<<<B_ * N_, 256>>>(res, f2_b);                // #10
}